// round 12
// baseline (speedup 1.0000x reference)
#include <cuda_runtime.h>
#include <cuda_fp16.h>

typedef unsigned int u32;

constexpr int BB   = 4096;
constexpr int SEQN = 49;
constexpr int CC   = 192;
constexpr int HH   = 6;
constexpr int DD   = 32;
constexpr int MROW = BB * SEQN;          // 200704 = 1568 * 128
constexpr float ATT_SCALE = 0.17677669529663687f;  // 32^-0.5

// ---------------- device scratch (static: no allocations allowed) ----------
__device__ __align__(16) __half g_q[(size_t)BB * HH * SEQN * DD];
__device__ __align__(16) __half g_k[(size_t)BB * HH * SEQN * DD];
__device__ __align__(16) __half g_v[(size_t)BB * HH * SEQN * DD];
__device__ __align__(16) __half g_o[(size_t)MROW * CC];       // [b*49+n][h*32+d]
__device__ __align__(16) __half g_wqkv_t[576 * 192];          // W^T [n][k]
__device__ __align__(16) __half g_wproj_t[192 * 192];

// ---------------- helpers ---------------------------------------------------
__device__ __forceinline__ u32 pack2(float a, float b) {
    __half2 h = __floats2half2_rn(a, b);
    return *reinterpret_cast<u32*>(&h);
}

__device__ __forceinline__ void mma16816(float* c, const u32* a, const u32* b) {
    asm volatile(
        "mma.sync.aligned.m16n8k16.row.col.f32.f16.f16.f32 "
        "{%0,%1,%2,%3}, {%4,%5,%6,%7}, {%8,%9}, {%0,%1,%2,%3};\n"
        : "+f"(c[0]), "+f"(c[1]), "+f"(c[2]), "+f"(c[3])
        : "r"(a[0]), "r"(a[1]), "r"(a[2]), "r"(a[3]), "r"(b[0]), "r"(b[1]));
}

__device__ __forceinline__ void ldsm4(u32* r, const void* p) {
    u32 a = (u32)__cvta_generic_to_shared(p);
    asm volatile("ldmatrix.sync.aligned.m8n8.x4.shared.b16 {%0,%1,%2,%3}, [%4];"
        : "=r"(r[0]), "=r"(r[1]), "=r"(r[2]), "=r"(r[3]) : "r"(a));
}
__device__ __forceinline__ void ldsm4t(u32* r, const void* p) {
    u32 a = (u32)__cvta_generic_to_shared(p);
    asm volatile("ldmatrix.sync.aligned.m8n8.x4.trans.shared.b16 {%0,%1,%2,%3}, [%4];"
        : "=r"(r[0]), "=r"(r[1]), "=r"(r[2]), "=r"(r[3]) : "r"(a));
}

__device__ __forceinline__ void cp16(void* sdst, const void* gsrc) {
    u32 s = (u32)__cvta_generic_to_shared(sdst);
    asm volatile("cp.async.cg.shared.global [%0], [%1], 16;\n" :: "r"(s), "l"(gsrc));
}
__device__ __forceinline__ void cp_commit() { asm volatile("cp.async.commit_group;\n"); }

// ---------------- prep: transpose + fp16-convert weights -------------------
__global__ void prep_kernel(const float* __restrict__ wq, const float* __restrict__ wp) {
    int i = blockIdx.x * blockDim.x + threadIdx.x;
    if (i < 576 * 192) {
        int n = i / 192, k = i - n * 192;
        g_wqkv_t[i] = __float2half_rn(wq[(size_t)k * 576 + n]);
    }
    if (i < 192 * 192) {
        int n = i / 192, k = i - n * 192;
        g_wproj_t[i] = __float2half_rn(wp[(size_t)k * 192 + n]);
    }
}

// ============================================================================
// Persistent-A GEMM: block computes C[128, NT*64], K=192.
// A (128x192 fp16) staged once in smem, all A-fragments hoisted to registers.
// B tiles (64x192) double-buffered via cp.async; ONE __syncthreads per n-tile.
// ============================================================================
struct GSmem {
    __half A[128][200];        // stride 200 halves (400B): conflict-free ldmatrix
    __half B[2][64][200];
};
constexpr unsigned GSMEM_BYTES = sizeof(GSmem);   // 102400

#define GEMM_ISSUE_B(Bg, nt, s)                                                \
    do {                                                                       \
        _Pragma("unroll")                                                      \
        for (int i_ = 0; i_ < 6; ++i_) {                                       \
            int idx_ = t + i_ * 256;                                           \
            int r_ = idx_ / 24, c_ = idx_ - r_ * 24;                           \
            cp16(&sm.B[s][r_][c_ * 8],                                         \
                 (Bg) + (size_t)((nt) * 64 + r_) * 192 + c_ * 8);              \
        }                                                                      \
        cp_commit();                                                           \
    } while (0)

#define GEMM_COMPUTE(s, acc)                                                   \
    do {                                                                       \
        _Pragma("unroll")                                                      \
        for (int ks = 0; ks < 12; ++ks) {                                      \
            u32 bfr[2][4];                                                     \
            ldsm4(bfr[0], &sm.B[s][wn + brow][ks * 16 + bcol]);                \
            ldsm4(bfr[1], &sm.B[s][wn + 16 + brow][ks * 16 + bcol]);           \
            _Pragma("unroll")                                                  \
            for (int mt = 0; mt < 2; ++mt) {                                   \
                mma16816(acc[mt][0], afr[ks][mt], &bfr[0][0]);                 \
                mma16816(acc[mt][1], afr[ks][mt], &bfr[0][2]);                 \
                mma16816(acc[mt][2], afr[ks][mt], &bfr[1][0]);                 \
                mma16816(acc[mt][3], afr[ks][mt], &bfr[1][2]);                 \
            }                                                                  \
        }                                                                      \
    } while (0)

// ---------------- GEMM 1: qkv = x @ Wqkv^T + b, scatter to q/k/v -----------
__global__ __launch_bounds__(256, 1) void gemm_qkv_kernel(const float* __restrict__ x,
                                                          const float* __restrict__ bias) {
    extern __shared__ __align__(16) char dsm[];
    GSmem& sm = *(GSmem*)dsm;
    const int t = threadIdx.x;
    const int warp = t >> 5, lane = t & 31;
    const int lr = lane >> 2, lw = lane & 3;
    const int wm = (warp >> 1) * 32, wn = (warp & 1) * 32;
    const int m0 = blockIdx.x * 128;
    const int lrow = lane & 15, lcol = (lane >> 4) << 3;
    const int brow = (lane & 7) + ((lane & 16) >> 1);
    const int bcol = (lane & 8);

    GEMM_ISSUE_B(g_wqkv_t, 0, 0);

    // A: fp32 x -> fp16 smem (24 float4 per thread)
    const float4* X4 = (const float4*)x + (size_t)m0 * 48;
#pragma unroll
    for (int i = 0; i < 24; ++i) {
        int idx = t + i * 256;
        int r = idx / 48, c = idx - r * 48;
        float4 f = X4[(size_t)r * 48 + c];
        __half2* dst = (__half2*)&sm.A[r][c * 4];
        dst[0] = __floats2half2_rn(f.x, f.y);
        dst[1] = __floats2half2_rn(f.z, f.w);
    }
    __syncthreads();

    // hoist all A fragments into registers
    u32 afr[12][2][4];
#pragma unroll
    for (int ks = 0; ks < 12; ++ks)
#pragma unroll
        for (int mt = 0; mt < 2; ++mt)
            ldsm4(afr[ks][mt], &sm.A[wm + mt * 16 + lrow][ks * 16 + lcol]);

    for (int nt = 0; nt < 9; ++nt) {
        asm volatile("cp.async.wait_group 0;\n" ::: "memory");
        __syncthreads();
        if (nt + 1 < 9) GEMM_ISSUE_B(g_wqkv_t, nt + 1, (nt + 1) & 1);
        const int s = nt & 1;
        float acc[2][4][4] = {};
        GEMM_COMPUTE(s, acc);

        // epilogue: +bias, scatter to q/k/v as [b][h][n][d]
        const int colbase = nt * 64 + wn;
#pragma unroll
        for (int mt = 0; mt < 2; ++mt) {
            int rg0 = m0 + wm + mt * 16 + lr;
            int rg1 = rg0 + 8;
            int b0 = rg0 / 49, p0 = rg0 - b0 * 49;
            int b1 = rg1 / 49, p1 = rg1 - b1 * 49;
#pragma unroll
            for (int j = 0; j < 4; ++j) {
                int col = colbase + j * 8 + lw * 2;
                int which = col / 192;
                int rem = col - which * 192;
                int hh = rem >> 5, dd = rem & 31;
                __half* dst = (which == 0) ? g_q : (which == 1) ? g_k : g_v;
                float bi0 = bias[col], bi1 = bias[col + 1];
                __half2 v0 = __floats2half2_rn(acc[mt][j][0] + bi0, acc[mt][j][1] + bi1);
                __half2 v1 = __floats2half2_rn(acc[mt][j][2] + bi0, acc[mt][j][3] + bi1);
                *(__half2*)(dst + ((size_t)(b0 * 6 + hh) * 49 + p0) * 32 + dd) = v0;
                *(__half2*)(dst + ((size_t)(b1 * 6 + hh) * 49 + p1) * 32 + dd) = v1;
            }
        }
    }
}

// ---------------- GEMM 2: out = O @ proj_w + proj_b (fp32 out) -------------
__global__ __launch_bounds__(256, 1) void gemm_proj_kernel(const float* __restrict__ bias,
                                                           float* __restrict__ out) {
    extern __shared__ __align__(16) char dsm[];
    GSmem& sm = *(GSmem*)dsm;
    const int t = threadIdx.x;
    const int warp = t >> 5, lane = t & 31;
    const int lr = lane >> 2, lw = lane & 3;
    const int wm = (warp >> 1) * 32, wn = (warp & 1) * 32;
    const int m0 = blockIdx.x * 128;
    const int lrow = lane & 15, lcol = (lane >> 4) << 3;
    const int brow = (lane & 7) + ((lane & 16) >> 1);
    const int bcol = (lane & 8);

    // A (fp16) via cp.async — its own group
#pragma unroll
    for (int i = 0; i < 12; ++i) {
        int idx = t + i * 256;
        int r = idx / 24, c = idx - r * 24;
        cp16(&sm.A[r][c * 8], g_o + (size_t)(m0 + r) * 192 + c * 8);
    }
    cp_commit();
    GEMM_ISSUE_B(g_wproj_t, 0, 0);

    asm volatile("cp.async.wait_group 1;\n" ::: "memory");   // A done
    __syncthreads();

    u32 afr[12][2][4];
#pragma unroll
    for (int ks = 0; ks < 12; ++ks)
#pragma unroll
        for (int mt = 0; mt < 2; ++mt)
            ldsm4(afr[ks][mt], &sm.A[wm + mt * 16 + lrow][ks * 16 + lcol]);

    for (int nt = 0; nt < 3; ++nt) {
        asm volatile("cp.async.wait_group 0;\n" ::: "memory");
        __syncthreads();
        if (nt + 1 < 3) GEMM_ISSUE_B(g_wproj_t, nt + 1, (nt + 1) & 1);
        const int s = nt & 1;
        float acc[2][4][4] = {};
        GEMM_COMPUTE(s, acc);

        const int colbase = nt * 64 + wn;
#pragma unroll
        for (int mt = 0; mt < 2; ++mt) {
            int rg0 = m0 + wm + mt * 16 + lr;
            int rg1 = rg0 + 8;
#pragma unroll
            for (int j = 0; j < 4; ++j) {
                int col = colbase + j * 8 + lw * 2;
                float bi0 = bias[col], bi1 = bias[col + 1];
                *(float2*)(out + (size_t)rg0 * 192 + col) =
                    make_float2(acc[mt][j][0] + bi0, acc[mt][j][1] + bi1);
                *(float2*)(out + (size_t)rg1 * 192 + col) =
                    make_float2(acc[mt][j][2] + bi0, acc[mt][j][3] + bi1);
            }
        }
    }
}

// ---------------- attention: 2 (b,h) per block, ldmatrix everywhere --------
__global__ __launch_bounds__(256) void attn_kernel(const float* __restrict__ mask) {
    __shared__ __align__(16) __half sQ[2][64][40];
    __shared__ __align__(16) __half sK[2][64][40];
    __shared__ __align__(16) __half sV[2][64][40];

    const int t = threadIdx.x;
    const int sub = t >> 7;
    const int tt = t & 127;
    const int warp = tt >> 5, lane = tt & 31;
    const int lr = lane >> 2, lw = lane & 3;
    const int lrow = lane & 15, lcol = (lane >> 4) << 3;
    const int brow = (lane & 7) + ((lane & 16) >> 1);
    const int bcol = (lane & 8);

    const int bh = blockIdx.x * 2 + sub;
    const int b = bh / 6, h = bh - b * 6;
    const int w = b & 63;

    // async q/k/v loads: 49 rows x 32 halves = 64 bytes = FOUR 16B chunks/row
    {
        const char* qg = (const char*)(g_q + (size_t)bh * 1568);
        const char* kg = (const char*)(g_k + (size_t)bh * 1568);
        const char* vg = (const char*)(g_v + (size_t)bh * 1568);
        for (int i = tt; i < 196; i += 128) {
            int r = i >> 2, c = i & 3;
            cp16(&sQ[sub][r][c * 8], qg + r * 64 + c * 16);
            cp16(&sK[sub][r][c * 8], kg + r * 64 + c * 16);
            cp16(&sV[sub][r][c * 8], vg + r * 64 + c * 16);
        }
        cp_commit();
        // zero V pad rows 49..63 (only V pad matters: P[j>=49] == 0, avoid NaN)
        for (int i = tt; i < 15 * 20; i += 128) {
            int r = 49 + i / 20, c = i - (i / 20) * 20;
            ((u32*)&sV[sub][r][0])[c] = 0u;
        }
        asm volatile("cp.async.wait_all;\n" ::: "memory");
    }
    __syncthreads();

    // Q fragments (16 rows per warp, k = 0..31)
    u32 qa[2][4];
    ldsm4(qa[0], &sQ[sub][warp * 16 + lrow][lcol]);
    ldsm4(qa[1], &sQ[sub][warp * 16 + lrow][16 + lcol]);

    // S = Q K^T : warp owns 16 rows x 64 cols
    float s[8][4] = {};
#pragma unroll
    for (int g = 0; g < 4; ++g) {
        u32 kb[2][4];
        ldsm4(kb[0], &sK[sub][g * 16 + brow][bcol]);        // k 0..15
        ldsm4(kb[1], &sK[sub][g * 16 + brow][16 + bcol]);   // k 16..31
        mma16816(s[2 * g],     qa[0], &kb[0][0]);
        mma16816(s[2 * g],     qa[1], &kb[1][0]);
        mma16816(s[2 * g + 1], qa[0], &kb[0][2]);
        mma16816(s[2 * g + 1], qa[1], &kb[1][2]);
    }

    // logits = s*scale + mask, masked softmax (rows r0, r1)
    const int r0 = warp * 16 + lr, r1 = r0 + 8;
    const float* m0p = mask + (size_t)w * 2401 + min(r0, 48) * 49;
    const float* m1p = mask + (size_t)w * 2401 + min(r1, 48) * 49;
#pragma unroll
    for (int nt = 0; nt < 8; ++nt) {
        int j0 = nt * 8 + lw * 2, j1 = j0 + 1;
        s[nt][0] = (j0 < 49) ? s[nt][0] * ATT_SCALE + m0p[j0] : -1e30f;
        s[nt][1] = (j1 < 49) ? s[nt][1] * ATT_SCALE + m0p[j1] : -1e30f;
        s[nt][2] = (j0 < 49) ? s[nt][2] * ATT_SCALE + m1p[j0] : -1e30f;
        s[nt][3] = (j1 < 49) ? s[nt][3] * ATT_SCALE + m1p[j1] : -1e30f;
    }
    float mx0 = -1e30f, mx1 = -1e30f;
#pragma unroll
    for (int nt = 0; nt < 8; ++nt) {
        mx0 = fmaxf(mx0, fmaxf(s[nt][0], s[nt][1]));
        mx1 = fmaxf(mx1, fmaxf(s[nt][2], s[nt][3]));
    }
    mx0 = fmaxf(mx0, __shfl_xor_sync(0xffffffffu, mx0, 1));
    mx0 = fmaxf(mx0, __shfl_xor_sync(0xffffffffu, mx0, 2));
    mx1 = fmaxf(mx1, __shfl_xor_sync(0xffffffffu, mx1, 1));
    mx1 = fmaxf(mx1, __shfl_xor_sync(0xffffffffu, mx1, 2));
    float sm0 = 0.f, sm1 = 0.f;
#pragma unroll
    for (int nt = 0; nt < 8; ++nt) {
        s[nt][0] = __expf(s[nt][0] - mx0);
        s[nt][1] = __expf(s[nt][1] - mx0);
        s[nt][2] = __expf(s[nt][2] - mx1);
        s[nt][3] = __expf(s[nt][3] - mx1);
        sm0 += s[nt][0] + s[nt][1];
        sm1 += s[nt][2] + s[nt][3];
    }
    sm0 += __shfl_xor_sync(0xffffffffu, sm0, 1);
    sm0 += __shfl_xor_sync(0xffffffffu, sm0, 2);
    sm1 += __shfl_xor_sync(0xffffffffu, sm1, 1);
    sm1 += __shfl_xor_sync(0xffffffffu, sm1, 2);
    const float inv0 = 1.f / sm0, inv1 = 1.f / sm1;

    // P (fp16 A-fragments), then O = P V  (V B-frags via ldmatrix.trans)
    u32 pa[4][4];
#pragma unroll
    for (int kk = 0; kk < 4; ++kk) {
        pa[kk][0] = pack2(s[2 * kk][0] * inv0, s[2 * kk][1] * inv0);
        pa[kk][1] = pack2(s[2 * kk][2] * inv1, s[2 * kk][3] * inv1);
        pa[kk][2] = pack2(s[2 * kk + 1][0] * inv0, s[2 * kk + 1][1] * inv0);
        pa[kk][3] = pack2(s[2 * kk + 1][2] * inv1, s[2 * kk + 1][3] * inv1);
    }
    float o[4][4] = {};
#pragma unroll
    for (int kk = 0; kk < 4; ++kk) {
        u32 vb[2][4];
        ldsm4t(vb[0], &sV[sub][kk * 16 + lrow][lcol]);        // d 0..15
        ldsm4t(vb[1], &sV[sub][kk * 16 + lrow][16 + lcol]);   // d 16..31
        mma16816(o[0], pa[kk], &vb[0][0]);
        mma16816(o[1], pa[kk], &vb[0][2]);
        mma16816(o[2], pa[kk], &vb[1][0]);
        mma16816(o[3], pa[kk], &vb[1][2]);
    }

    // store O as [b*49+n][h*32+d] fp16 for proj GEMM
#pragma unroll
    for (int dt = 0; dt < 4; ++dt) {
        int dd = dt * 8 + lw * 2;
        if (r0 < 49)
            *(__half2*)(g_o + ((size_t)(b * 49 + r0) * 6 + h) * 32 + dd) =
                __floats2half2_rn(o[dt][0], o[dt][1]);
        if (r1 < 49)
            *(__half2*)(g_o + ((size_t)(b * 49 + r1) * 6 + h) * 32 + dd) =
                __floats2half2_rn(o[dt][2], o[dt][3]);
    }
}

// ---------------- launch ----------------------------------------------------
extern "C" void kernel_launch(void* const* d_in, const int* in_sizes, int n_in,
                              void* d_out, int out_size) {
    const float* x      = (const float*)d_in[0];
    const float* mask   = (const float*)d_in[1];
    const float* qkv_w  = (const float*)d_in[2];
    const float* qkv_b  = (const float*)d_in[3];
    const float* proj_w = (const float*)d_in[4];
    const float* proj_b = (const float*)d_in[5];
    float* out = (float*)d_out;

    cudaFuncSetAttribute(gemm_qkv_kernel,
                         cudaFuncAttributeMaxDynamicSharedMemorySize, GSMEM_BYTES);
    cudaFuncSetAttribute(gemm_proj_kernel,
                         cudaFuncAttributeMaxDynamicSharedMemorySize, GSMEM_BYTES);

    prep_kernel<<<(576 * 192 + 255) / 256, 256>>>(qkv_w, proj_w);
    gemm_qkv_kernel<<<MROW / 128, 256, GSMEM_BYTES>>>(x, qkv_b);
    attn_kernel<<<BB * HH / 2, 256>>>(mask);
    gemm_proj_kernel<<<MROW / 128, 256, GSMEM_BYTES>>>(proj_b, out);
}

// round 13
// speedup vs baseline: 1.0156x; 1.0156x over previous
#include <cuda_runtime.h>
#include <cuda_fp16.h>

typedef unsigned int u32;

constexpr int BB   = 4096;
constexpr int SEQN = 49;
constexpr int CC   = 192;
constexpr int HH   = 6;
constexpr int DD   = 32;
constexpr int MROW = BB * SEQN;          // 200704 = 1568 * 128
constexpr float ATT_SCALE = 0.17677669529663687f;  // 32^-0.5

// ---------------- device scratch (static: no allocations allowed) ----------
__device__ __align__(16) __half g_q[(size_t)BB * HH * SEQN * DD];
__device__ __align__(16) __half g_k[(size_t)BB * HH * SEQN * DD];
__device__ __align__(16) __half g_v[(size_t)BB * HH * SEQN * DD];
__device__ __align__(16) __half g_o[(size_t)MROW * CC];       // [b*49+n][h*32+d]
__device__ __align__(16) __half g_wqkv_t[576 * 192];          // W^T [n][k]
__device__ __align__(16) __half g_wproj_t[192 * 192];

// ---------------- helpers ---------------------------------------------------
__device__ __forceinline__ u32 pack2(float a, float b) {
    __half2 h = __floats2half2_rn(a, b);
    return *reinterpret_cast<u32*>(&h);
}

__device__ __forceinline__ void mma16816(float* c, const u32* a, const u32* b) {
    asm volatile(
        "mma.sync.aligned.m16n8k16.row.col.f32.f16.f16.f32 "
        "{%0,%1,%2,%3}, {%4,%5,%6,%7}, {%8,%9}, {%0,%1,%2,%3};\n"
        : "+f"(c[0]), "+f"(c[1]), "+f"(c[2]), "+f"(c[3])
        : "r"(a[0]), "r"(a[1]), "r"(a[2]), "r"(a[3]), "r"(b[0]), "r"(b[1]));
}

__device__ __forceinline__ void ldsm4(u32* r, const void* p) {
    u32 a = (u32)__cvta_generic_to_shared(p);
    asm volatile("ldmatrix.sync.aligned.m8n8.x4.shared.b16 {%0,%1,%2,%3}, [%4];"
        : "=r"(r[0]), "=r"(r[1]), "=r"(r[2]), "=r"(r[3]) : "r"(a));
}
__device__ __forceinline__ void ldsm4t(u32* r, const void* p) {
    u32 a = (u32)__cvta_generic_to_shared(p);
    asm volatile("ldmatrix.sync.aligned.m8n8.x4.trans.shared.b16 {%0,%1,%2,%3}, [%4];"
        : "=r"(r[0]), "=r"(r[1]), "=r"(r[2]), "=r"(r[3]) : "r"(a));
}

__device__ __forceinline__ void cp16(void* sdst, const void* gsrc) {
    u32 s = (u32)__cvta_generic_to_shared(sdst);
    asm volatile("cp.async.cg.shared.global [%0], [%1], 16;\n" :: "r"(s), "l"(gsrc));
}
__device__ __forceinline__ void cp_commit() { asm volatile("cp.async.commit_group;\n"); }

// ---------------- prep: transpose + fp16-convert weights -------------------
__global__ void prep_kernel(const float* __restrict__ wq, const float* __restrict__ wp) {
    int i = blockIdx.x * blockDim.x + threadIdx.x;
    if (i < 576 * 192) {
        int n = i / 192, k = i - n * 192;
        g_wqkv_t[i] = __float2half_rn(wq[(size_t)k * 576 + n]);
    }
    if (i < 192 * 192) {
        int n = i / 192, k = i - n * 192;
        g_wproj_t[i] = __float2half_rn(wp[(size_t)k * 192 + n]);
    }
}

// ============================================================================
// Persistent-A GEMM: block computes C[128, NT*64], K=192.
// A (128x192 fp16) staged once in smem, all A-fragments hoisted to registers.
// B tiles (64x192) double-buffered via cp.async; ONE __syncthreads per n-tile.
// ============================================================================
struct GSmem {
    __half A[128][200];        // stride 200 halves (400B): conflict-free ldmatrix
    __half B[2][64][200];
};
constexpr unsigned GSMEM_BYTES = sizeof(GSmem);   // 102400

#define GEMM_ISSUE_B(Bg, nt, s)                                                \
    do {                                                                       \
        _Pragma("unroll")                                                      \
        for (int i_ = 0; i_ < 6; ++i_) {                                       \
            int idx_ = t + i_ * 256;                                           \
            int r_ = idx_ / 24, c_ = idx_ - r_ * 24;                           \
            cp16(&sm.B[s][r_][c_ * 8],                                         \
                 (Bg) + (size_t)((nt) * 64 + r_) * 192 + c_ * 8);              \
        }                                                                      \
        cp_commit();                                                           \
    } while (0)

#define GEMM_COMPUTE(s, acc)                                                   \
    do {                                                                       \
        _Pragma("unroll")                                                      \
        for (int ks = 0; ks < 12; ++ks) {                                      \
            u32 bfr[2][4];                                                     \
            ldsm4(bfr[0], &sm.B[s][wn + brow][ks * 16 + bcol]);                \
            ldsm4(bfr[1], &sm.B[s][wn + 16 + brow][ks * 16 + bcol]);           \
            _Pragma("unroll")                                                  \
            for (int mt = 0; mt < 2; ++mt) {                                   \
                mma16816(acc[mt][0], afr[ks][mt], &bfr[0][0]);                 \
                mma16816(acc[mt][1], afr[ks][mt], &bfr[0][2]);                 \
                mma16816(acc[mt][2], afr[ks][mt], &bfr[1][0]);                 \
                mma16816(acc[mt][3], afr[ks][mt], &bfr[1][2]);                 \
            }                                                                  \
        }                                                                      \
    } while (0)

// ---------------- GEMM 1: qkv = x @ Wqkv^T + b, scatter to q/k/v -----------
__global__ __launch_bounds__(256, 1) void gemm_qkv_kernel(const float* __restrict__ x,
                                                          const float* __restrict__ bias) {
    extern __shared__ __align__(16) char dsm[];
    GSmem& sm = *(GSmem*)dsm;
    const int t = threadIdx.x;
    const int warp = t >> 5, lane = t & 31;
    const int lr = lane >> 2, lw = lane & 3;
    const int wm = (warp >> 1) * 32, wn = (warp & 1) * 32;
    const int m0 = blockIdx.x * 128;
    const int lrow = lane & 15, lcol = (lane >> 4) << 3;
    const int brow = (lane & 7) + ((lane & 16) >> 1);
    const int bcol = (lane & 8);

    GEMM_ISSUE_B(g_wqkv_t, 0, 0);

    // A: fp32 x -> fp16 smem (24 float4 per thread)
    const float4* X4 = (const float4*)x + (size_t)m0 * 48;
#pragma unroll
    for (int i = 0; i < 24; ++i) {
        int idx = t + i * 256;
        int r = idx / 48, c = idx - r * 48;
        float4 f = X4[(size_t)r * 48 + c];
        __half2* dst = (__half2*)&sm.A[r][c * 4];
        dst[0] = __floats2half2_rn(f.x, f.y);
        dst[1] = __floats2half2_rn(f.z, f.w);
    }
    __syncthreads();

    // hoist all A fragments into registers
    u32 afr[12][2][4];
#pragma unroll
    for (int ks = 0; ks < 12; ++ks)
#pragma unroll
        for (int mt = 0; mt < 2; ++mt)
            ldsm4(afr[ks][mt], &sm.A[wm + mt * 16 + lrow][ks * 16 + lcol]);

    for (int nt = 0; nt < 9; ++nt) {
        asm volatile("cp.async.wait_group 0;\n" ::: "memory");
        __syncthreads();
        if (nt + 1 < 9) GEMM_ISSUE_B(g_wqkv_t, nt + 1, (nt + 1) & 1);
        const int s = nt & 1;
        float acc[2][4][4] = {};
        GEMM_COMPUTE(s, acc);

        // epilogue: +bias, scatter to q/k/v as [b][h][n][d]
        const int colbase = nt * 64 + wn;
#pragma unroll
        for (int mt = 0; mt < 2; ++mt) {
            int rg0 = m0 + wm + mt * 16 + lr;
            int rg1 = rg0 + 8;
            int b0 = rg0 / 49, p0 = rg0 - b0 * 49;
            int b1 = rg1 / 49, p1 = rg1 - b1 * 49;
#pragma unroll
            for (int j = 0; j < 4; ++j) {
                int col = colbase + j * 8 + lw * 2;
                int which = col / 192;
                int rem = col - which * 192;
                int hh = rem >> 5, dd = rem & 31;
                __half* dst = (which == 0) ? g_q : (which == 1) ? g_k : g_v;
                float bi0 = bias[col], bi1 = bias[col + 1];
                __half2 v0 = __floats2half2_rn(acc[mt][j][0] + bi0, acc[mt][j][1] + bi1);
                __half2 v1 = __floats2half2_rn(acc[mt][j][2] + bi0, acc[mt][j][3] + bi1);
                *(__half2*)(dst + ((size_t)(b0 * 6 + hh) * 49 + p0) * 32 + dd) = v0;
                *(__half2*)(dst + ((size_t)(b1 * 6 + hh) * 49 + p1) * 32 + dd) = v1;
            }
        }
    }
}

// ---------------- GEMM 2: out = O @ proj_w + proj_b (fp32 out) -------------
__global__ __launch_bounds__(256, 1) void gemm_proj_kernel(const float* __restrict__ bias,
                                                           float* __restrict__ out) {
    extern __shared__ __align__(16) char dsm[];
    GSmem& sm = *(GSmem*)dsm;
    const int t = threadIdx.x;
    const int warp = t >> 5, lane = t & 31;
    const int lr = lane >> 2, lw = lane & 3;
    const int wm = (warp >> 1) * 32, wn = (warp & 1) * 32;
    const int m0 = blockIdx.x * 128;
    const int lrow = lane & 15, lcol = (lane >> 4) << 3;
    const int brow = (lane & 7) + ((lane & 16) >> 1);
    const int bcol = (lane & 8);

    // A (fp16) via cp.async — its own group
#pragma unroll
    for (int i = 0; i < 12; ++i) {
        int idx = t + i * 256;
        int r = idx / 24, c = idx - r * 24;
        cp16(&sm.A[r][c * 8], g_o + (size_t)(m0 + r) * 192 + c * 8);
    }
    cp_commit();
    GEMM_ISSUE_B(g_wproj_t, 0, 0);

    asm volatile("cp.async.wait_group 1;\n" ::: "memory");   // A done
    __syncthreads();

    u32 afr[12][2][4];
#pragma unroll
    for (int ks = 0; ks < 12; ++ks)
#pragma unroll
        for (int mt = 0; mt < 2; ++mt)
            ldsm4(afr[ks][mt], &sm.A[wm + mt * 16 + lrow][ks * 16 + lcol]);

    for (int nt = 0; nt < 3; ++nt) {
        asm volatile("cp.async.wait_group 0;\n" ::: "memory");
        __syncthreads();
        if (nt + 1 < 3) GEMM_ISSUE_B(g_wproj_t, nt + 1, (nt + 1) & 1);
        const int s = nt & 1;
        float acc[2][4][4] = {};
        GEMM_COMPUTE(s, acc);

        const int colbase = nt * 64 + wn;
#pragma unroll
        for (int mt = 0; mt < 2; ++mt) {
            int rg0 = m0 + wm + mt * 16 + lr;
            int rg1 = rg0 + 8;
#pragma unroll
            for (int j = 0; j < 4; ++j) {
                int col = colbase + j * 8 + lw * 2;
                float bi0 = bias[col], bi1 = bias[col + 1];
                *(float2*)(out + (size_t)rg0 * 192 + col) =
                    make_float2(acc[mt][j][0] + bi0, acc[mt][j][1] + bi1);
                *(float2*)(out + (size_t)rg1 * 192 + col) =
                    make_float2(acc[mt][j][2] + bi0, acc[mt][j][3] + bi1);
            }
        }
    }
}

// ---------------- attention: 2 (b,h) per block, ldmatrix everywhere --------
__global__ __launch_bounds__(256) void attn_kernel(const float* __restrict__ mask) {
    __shared__ __align__(16) __half sQ[2][64][40];
    __shared__ __align__(16) __half sK[2][64][40];
    __shared__ __align__(16) __half sV[2][64][40];

    const int t = threadIdx.x;
    const int sub = t >> 7;
    const int tt = t & 127;
    const int warp = tt >> 5, lane = tt & 31;
    const int lr = lane >> 2, lw = lane & 3;
    const int lrow = lane & 15, lcol = (lane >> 4) << 3;
    const int brow = (lane & 7) + ((lane & 16) >> 1);
    const int bcol = (lane & 8);

    const int bh = blockIdx.x * 2 + sub;
    const int b = bh / 6, h = bh - b * 6;
    const int w = b & 63;

    // async q/k/v loads: 49 rows x 32 halves = 64 bytes = FOUR 16B chunks/row
    {
        const char* qg = (const char*)(g_q + (size_t)bh * 1568);
        const char* kg = (const char*)(g_k + (size_t)bh * 1568);
        const char* vg = (const char*)(g_v + (size_t)bh * 1568);
        for (int i = tt; i < 196; i += 128) {
            int r = i >> 2, c = i & 3;
            cp16(&sQ[sub][r][c * 8], qg + r * 64 + c * 16);
            cp16(&sK[sub][r][c * 8], kg + r * 64 + c * 16);
            cp16(&sV[sub][r][c * 8], vg + r * 64 + c * 16);
        }
        cp_commit();
        // zero V pad rows 49..63 (only V pad matters: P[j>=49] == 0, avoid NaN)
        for (int i = tt; i < 15 * 20; i += 128) {
            int r = 49 + i / 20, c = i - (i / 20) * 20;
            ((u32*)&sV[sub][r][0])[c] = 0u;
        }
        asm volatile("cp.async.wait_all;\n" ::: "memory");
    }
    __syncthreads();

    // Q fragments (16 rows per warp, k = 0..31)
    u32 qa[2][4];
    ldsm4(qa[0], &sQ[sub][warp * 16 + lrow][lcol]);
    ldsm4(qa[1], &sQ[sub][warp * 16 + lrow][16 + lcol]);

    // S = Q K^T : warp owns 16 rows x 64 cols
    float s[8][4] = {};
#pragma unroll
    for (int g = 0; g < 4; ++g) {
        u32 kb[2][4];
        ldsm4(kb[0], &sK[sub][g * 16 + brow][bcol]);        // k 0..15
        ldsm4(kb[1], &sK[sub][g * 16 + brow][16 + bcol]);   // k 16..31
        mma16816(s[2 * g],     qa[0], &kb[0][0]);
        mma16816(s[2 * g],     qa[1], &kb[1][0]);
        mma16816(s[2 * g + 1], qa[0], &kb[0][2]);
        mma16816(s[2 * g + 1], qa[1], &kb[1][2]);
    }

    // logits = s*scale + mask, masked softmax (rows r0, r1)
    const int r0 = warp * 16 + lr, r1 = r0 + 8;
    const float* m0p = mask + (size_t)w * 2401 + min(r0, 48) * 49;
    const float* m1p = mask + (size_t)w * 2401 + min(r1, 48) * 49;
#pragma unroll
    for (int nt = 0; nt < 8; ++nt) {
        int j0 = nt * 8 + lw * 2, j1 = j0 + 1;
        s[nt][0] = (j0 < 49) ? s[nt][0] * ATT_SCALE + m0p[j0] : -1e30f;
        s[nt][1] = (j1 < 49) ? s[nt][1] * ATT_SCALE + m0p[j1] : -1e30f;
        s[nt][2] = (j0 < 49) ? s[nt][2] * ATT_SCALE + m1p[j0] : -1e30f;
        s[nt][3] = (j1 < 49) ? s[nt][3] * ATT_SCALE + m1p[j1] : -1e30f;
    }
    float mx0 = -1e30f, mx1 = -1e30f;
#pragma unroll
    for (int nt = 0; nt < 8; ++nt) {
        mx0 = fmaxf(mx0, fmaxf(s[nt][0], s[nt][1]));
        mx1 = fmaxf(mx1, fmaxf(s[nt][2], s[nt][3]));
    }
    mx0 = fmaxf(mx0, __shfl_xor_sync(0xffffffffu, mx0, 1));
    mx0 = fmaxf(mx0, __shfl_xor_sync(0xffffffffu, mx0, 2));
    mx1 = fmaxf(mx1, __shfl_xor_sync(0xffffffffu, mx1, 1));
    mx1 = fmaxf(mx1, __shfl_xor_sync(0xffffffffu, mx1, 2));
    float sm0 = 0.f, sm1 = 0.f;
#pragma unroll
    for (int nt = 0; nt < 8; ++nt) {
        s[nt][0] = __expf(s[nt][0] - mx0);
        s[nt][1] = __expf(s[nt][1] - mx0);
        s[nt][2] = __expf(s[nt][2] - mx1);
        s[nt][3] = __expf(s[nt][3] - mx1);
        sm0 += s[nt][0] + s[nt][1];
        sm1 += s[nt][2] + s[nt][3];
    }
    sm0 += __shfl_xor_sync(0xffffffffu, sm0, 1);
    sm0 += __shfl_xor_sync(0xffffffffu, sm0, 2);
    sm1 += __shfl_xor_sync(0xffffffffu, sm1, 1);
    sm1 += __shfl_xor_sync(0xffffffffu, sm1, 2);
    const float inv0 = 1.f / sm0, inv1 = 1.f / sm1;

    // P (fp16 A-fragments), then O = P V  (V B-frags via ldmatrix.trans)
    u32 pa[4][4];
#pragma unroll
    for (int kk = 0; kk < 4; ++kk) {
        pa[kk][0] = pack2(s[2 * kk][0] * inv0, s[2 * kk][1] * inv0);
        pa[kk][1] = pack2(s[2 * kk][2] * inv1, s[2 * kk][3] * inv1);
        pa[kk][2] = pack2(s[2 * kk + 1][0] * inv0, s[2 * kk + 1][1] * inv0);
        pa[kk][3] = pack2(s[2 * kk + 1][2] * inv1, s[2 * kk + 1][3] * inv1);
    }
    float o[4][4] = {};
#pragma unroll
    for (int kk = 0; kk < 4; ++kk) {
        u32 vb[2][4];
        ldsm4t(vb[0], &sV[sub][kk * 16 + lrow][lcol]);        // d 0..15
        ldsm4t(vb[1], &sV[sub][kk * 16 + lrow][16 + lcol]);   // d 16..31
        mma16816(o[0], pa[kk], &vb[0][0]);
        mma16816(o[1], pa[kk], &vb[0][2]);
        mma16816(o[2], pa[kk], &vb[1][0]);
        mma16816(o[3], pa[kk], &vb[1][2]);
    }

    // store O as [b*49+n][h*32+d] fp16 for proj GEMM
#pragma unroll
    for (int dt = 0; dt < 4; ++dt) {
        int dd = dt * 8 + lw * 2;
        if (r0 < 49)
            *(__half2*)(g_o + ((size_t)(b * 49 + r0) * 6 + h) * 32 + dd) =
                __floats2half2_rn(o[dt][0], o[dt][1]);
        if (r1 < 49)
            *(__half2*)(g_o + ((size_t)(b * 49 + r1) * 6 + h) * 32 + dd) =
                __floats2half2_rn(o[dt][2], o[dt][3]);
    }
}

// ---------------- launch ----------------------------------------------------
extern "C" void kernel_launch(void* const* d_in, const int* in_sizes, int n_in,
                              void* d_out, int out_size) {
    const float* x      = (const float*)d_in[0];
    const float* mask   = (const float*)d_in[1];
    const float* qkv_w  = (const float*)d_in[2];
    const float* qkv_b  = (const float*)d_in[3];
    const float* proj_w = (const float*)d_in[4];
    const float* proj_b = (const float*)d_in[5];
    float* out = (float*)d_out;

    cudaFuncSetAttribute(gemm_qkv_kernel,
                         cudaFuncAttributeMaxDynamicSharedMemorySize, GSMEM_BYTES);
    cudaFuncSetAttribute(gemm_proj_kernel,
                         cudaFuncAttributeMaxDynamicSharedMemorySize, GSMEM_BYTES);

    prep_kernel<<<(576 * 192 + 255) / 256, 256>>>(qkv_w, proj_w);
    gemm_qkv_kernel<<<MROW / 128, 256, GSMEM_BYTES>>>(x, qkv_b);
    attn_kernel<<<BB * HH / 2, 256>>>(mask);
    gemm_proj_kernel<<<MROW / 128, 256, GSMEM_BYTES>>>(proj_b, out);
}